// round 4
// baseline (speedup 1.0000x reference)
#include <cuda_runtime.h>
#include <math.h>

#define D    256
#define L    512
#define NU   64

// word kernel decomposition: 8 batch groups x 16 hidden slices = 128 CTAs
#define GB   8
#define UPG  8          // utterances per group
#define GH   16
#define HPS  16         // hidden units per slice
#define RPS  48         // gate rows per slice (3*HPS)
#define WT   384        // 12 warps
#define XST  272        // x/h SMEM row stride in floats (16B aligned, conflict-free)

typedef unsigned long long ull;

// ---------------- device scratch (static; no allocations) ----------------
__device__ float g_h_hist[(size_t)L * NU * D];   // word-GRU hidden history (33.5 MB)
__device__ float g_utt[NU * D];                  // utterance vectors after word attn-pool
__device__ int   g_flag[GB * GH];                // per-(group,slice) step flags

// ---------------- low-level helpers ----------------
__device__ __forceinline__ ull ffma2(ull a, ull b, ull c) {
    ull d;
    asm("fma.rn.f32x2 %0, %1, %2, %3;" : "=l"(d) : "l"(a), "l"(b), "l"(c));
    return d;
}
__device__ __forceinline__ float2 unpk2(ull v) {
    float2 r;
    asm("mov.b64 {%0, %1}, %2;" : "=f"(r.x), "=f"(r.y) : "l"(v));
    return r;
}
__device__ __forceinline__ int ld_acquire(const int* p) {
    int v;
    asm volatile("ld.acquire.gpu.b32 %0, [%1];" : "=r"(v) : "l"(p) : "memory");
    return v;
}
__device__ __forceinline__ void st_release(int* p, int v) {
    asm volatile("st.release.gpu.b32 [%0], %1;" :: "l"(p), "r"(v) : "memory");
}
__device__ __forceinline__ float sigmoidf_(float x) { return 1.f / (1.f + __expf(-x)); }

// gate row -> global weight row (gate order r, z, n)
__device__ __forceinline__ int gate_row(int i0, int lr) {
    return (lr < 16) ? (i0 + lr)
         : (lr < 32) ? (256 + i0 + (lr - 16))
                     : (512 + i0 + (lr - 32));
}

// accumulate one GEMV phase into acc[32] (u64, k-packed); weights in regs
__device__ __forceinline__ void accum_phase(ull acc[32], const ulonglong2 w[4][2],
                                            const float* __restrict__ xb, int lane) {
#pragma unroll
    for (int u = 0; u < 8; ++u) {
        const ulonglong2* xu = (const ulonglong2*)(xb + u * XST);
        ulonglong2 x0 = xu[lane];        // pass 0: k = lane*4 .. +3
        ulonglong2 x1 = xu[32 + lane];   // pass 1: k = 128 + lane*4 .. +3
#pragma unroll
        for (int r = 0; r < 4; ++r) {
            ull a = acc[r * 8 + u];
            a = ffma2(w[r][0].x, x0.x, a);
            a = ffma2(w[r][0].y, x0.y, a);
            a = ffma2(w[r][1].x, x1.x, a);
            a = ffma2(w[r][1].y, x1.y, a);
            acc[r * 8 + u] = a;
        }
    }
}

// recursive-halving butterfly: lane l returns full sum for output l (= r2*8+u)
__device__ __forceinline__ float reduce32(ull acc[32], int lane) {
    float v[32];
#pragma unroll
    for (int j = 0; j < 32; ++j) { float2 p = unpk2(acc[j]); v[j] = p.x + p.y; }
#pragma unroll
    for (int m = 16; m >= 1; m >>= 1) {
        bool hi = (lane & m) != 0;
#pragma unroll
        for (int j = 0; j < m; ++j) {
            float send = hi ? v[j] : v[j + m];
            float got  = __shfl_xor_sync(0xffffffffu, send, m);
            v[j] = (hi ? v[j + m] : v[j]) + got;
        }
    }
    return v[0];
}

// ---------------- reset: zero flags each launch (graph-replay safe) ----------------
__global__ void reset_kernel() {
    if (threadIdx.x < GB * GH) g_flag[threadIdx.x] = 0;
}

// ---------------- word GRU persistent kernel (weights in registers) ----------------
__global__ void __launch_bounds__(WT, 1)
word_kernel(const int* __restrict__ tokens, const float* __restrict__ embed,
            const float* __restrict__ Wih, const float* __restrict__ Whh,
            const float* __restrict__ bih, const float* __restrict__ bhh) {
    __shared__ float s_x[2 * 8 * XST];    // double-buffered x_t
    __shared__ float s_h[8 * XST];        // h_{t-1} staged
    __shared__ float s_gih[WT];           // rz: combined preact; n: xn+bih
    __shared__ float s_ghh[128];          // n rows only: hn+bhh
    __shared__ float s_bih[RPS];
    __shared__ float s_bhh[RPS];

    const int g    = blockIdx.x >> 4;     // batch group
    const int sl   = blockIdx.x & 15;     // hidden slice
    const int i0   = sl * HPS;
    const int b0   = g * UPG;
    const int tid  = threadIdx.x;
    const int wp   = tid >> 5;            // warp id (0..11); 0-3:r 4-7:z 8-11:n
    const int lane = tid & 31;
    const bool have2  = (tid < 128);
    const bool n_warp = (wp >= 8);

    // ---- prologue: weights -> registers ----
    ulonglong2 wih[4][2], whh[4][2];
#pragma unroll
    for (int r = 0; r < 4; ++r) {
        int grow = gate_row(i0, wp * 4 + r);
#pragma unroll
        for (int p = 0; p < 2; ++p) {
            wih[r][p] = *(const ulonglong2*)(Wih + (size_t)grow * D + p * 128 + lane * 4);
            whh[r][p] = *(const ulonglong2*)(Whh + (size_t)grow * D + p * 128 + lane * 4);
        }
    }
    if (tid < RPS) {
        int grow = gate_row(i0, tid);
        s_bih[tid] = bih[grow];
        s_bhh[tid] = bhh[grow];
    }
    for (int idx = tid; idx < UPG * 64; idx += WT) {
        int uu = idx >> 6, k4 = idx & 63;
        int tok = tokens[(b0 + uu) * L + 0];
        ((float4*)(s_x + uu * XST))[k4] = ((const float4*)(embed + (size_t)tok * D))[k4];
        ((float4*)(s_h + uu * XST))[k4] = make_float4(0.f, 0.f, 0.f, 0.f);
    }
    __syncthreads();

    const int   myrow = wp * 4 + (lane >> 3);   // owned output row after reduction
    const float mybih = s_bih[myrow];
    const float mybhh = s_bhh[myrow];

    for (int t = 0; t < L; ++t) {
        const int buf = t & 1;

        // (A) prefetch embedding rows for t+1 into regs
        float4 pf0 = make_float4(0.f, 0.f, 0.f, 0.f);
        float4 pf1 = make_float4(0.f, 0.f, 0.f, 0.f);
        if (t + 1 < L) {
            int idx = tid, uu = idx >> 6, k4 = idx & 63;
            int tok = tokens[(b0 + uu) * L + (t + 1)];
            pf0 = ((const float4*)(embed + (size_t)tok * D))[k4];
            if (have2) {
                idx = tid + WT; uu = idx >> 6; k4 = idx & 63;
                tok = tokens[(b0 + uu) * L + (t + 1)];
                pf1 = ((const float4*)(embed + (size_t)tok * D))[k4];
            }
        }

        // (B) ih phase
        ull acc[32];
#pragma unroll
        for (int j = 0; j < 32; ++j) acc[j] = 0ull;
        accum_phase(acc, wih, s_x + buf * (8 * XST), lane);

        // (C) n-warps: reduce xn now (needed separately from hn)
        if (n_warp) {
            s_gih[tid] = reduce32(acc, lane) + mybih;
#pragma unroll
            for (int j = 0; j < 32; ++j) acc[j] = 0ull;
        }

        // (D) stage h_{t-1}: per-warp flag poll + copy
        if (t > 0) {
            const float* hsrc = g_h_hist + (size_t)(t - 1) * NU * D + (size_t)b0 * D;
            for (int s = wp; s < GH; s += 12) {
                const int* fp = &g_flag[g * GH + s];
                while (ld_acquire(fp) < t) { }
                int uu = lane >> 2, k4 = lane & 3;
                float4 v = *(const float4*)(hsrc + (size_t)uu * D + s * HPS + k4 * 4);
                *(float4*)(s_h + uu * XST + s * HPS + k4 * 4) = v;
            }
        }
        __syncthreads();

        // (E) hh phase (rz: same acc -> combined; n: fresh acc)
        accum_phase(acc, whh, s_h, lane);

        // (F) park prefetched x_{t+1}
        if (t + 1 < L) {
            int idx = tid, uu = idx >> 6, k4 = idx & 63;
            ((float4*)(s_x + (buf ^ 1) * (8 * XST) + uu * XST))[k4] = pf0;
            if (have2) {
                idx = tid + WT; uu = idx >> 6; k4 = idx & 63;
                ((float4*)(s_x + (buf ^ 1) * (8 * XST) + uu * XST))[k4] = pf1;
            }
        }

        // (G) final reduction
        float red = reduce32(acc, lane);
        if (n_warp) s_ghh[tid - 256] = red + mybhh;
        else        s_gih[tid] = red + mybih + mybhh;
        __syncthreads();

        // (H) gates + hidden update + publish (coalesced STG)
        if (tid < 128) {
            int ii = tid & 15, uu = tid >> 4;
            float rc = s_gih[ii * 8 + uu];          // xr+hr+biases
            float zc = s_gih[(16 + ii) * 8 + uu];   // xz+hz+biases
            float xn = s_gih[(32 + ii) * 8 + uu];   // xn+bih
            float hn = s_ghh[ii * 8 + uu];          // hn+bhh
            float r = sigmoidf_(rc);
            float z = sigmoidf_(zc);
            float n = tanhf(xn + r * hn);
            float hprev = s_h[uu * XST + i0 + ii];
            float hnew = (1.f - z) * n + z * hprev;
            g_h_hist[(size_t)t * NU * D + (size_t)(b0 + uu) * D + (i0 + ii)] = hnew;
        }
        __syncthreads();

        // (I) publish flag
        if (tid == 0) {
            __threadfence();
            st_release(&g_flag[g * GH + sl], t + 1);
        }
    }
}

// ---------------- word-level attention pool: h_hist -> g_utt ----------------
__global__ void __launch_bounds__(256, 1)
pool_kernel(const float* __restrict__ ua_w) {
    __shared__ float s_w[D];
    __shared__ float s_l[L];
    __shared__ float s_red[32];
    const int b = blockIdx.x, tid = threadIdx.x;
    const int lane = tid & 31, wpp = tid >> 5;

    s_w[tid] = ua_w[tid];
    __syncthreads();

    const float* base = g_h_hist + (size_t)b * D;
    for (int tt = 0; tt < 64; ++tt) {
        int t = wpp * 64 + tt;
        const float* row = base + (size_t)t * NU * D;
        float p = 0.f;
#pragma unroll
        for (int j = 0; j < 8; ++j) p += row[lane + 32 * j] * s_w[lane + 32 * j];
        for (int off = 16; off; off >>= 1) p += __shfl_down_sync(0xffffffffu, p, off);
        if (lane == 0) s_l[t] = p;   // ua_b omitted: softmax-invariant
    }
    __syncthreads();

    float m = -1e30f;
    for (int t = tid; t < L; t += 256) m = fmaxf(m, s_l[t]);
    for (int off = 16; off; off >>= 1) m = fmaxf(m, __shfl_xor_sync(0xffffffffu, m, off));
    if (lane == 0) s_red[wpp] = m;
    __syncthreads();
    if (tid == 0) {
        float mm = s_red[0];
#pragma unroll
        for (int i = 1; i < 8; ++i) mm = fmaxf(mm, s_red[i]);
        s_red[16] = mm;
    }
    __syncthreads();
    m = s_red[16];
    float ssum = 0.f;
    for (int t = tid; t < L; t += 256) {
        float e = expf(s_l[t] - m);
        s_l[t] = e;
        ssum += e;
    }
    for (int off = 16; off; off >>= 1) ssum += __shfl_xor_sync(0xffffffffu, ssum, off);
    if (lane == 0) s_red[wpp] = ssum;
    __syncthreads();
    if (tid == 0) {
        float ss = 0.f;
#pragma unroll
        for (int i = 0; i < 8; ++i) ss += s_red[i];
        s_red[17] = ss;
    }
    __syncthreads();
    const float inv = 1.f / s_red[17];

    float acc = 0.f;
#pragma unroll 8
    for (int t = 0; t < L; ++t) acc += s_l[t] * base[(size_t)t * NU * D + tid];
    g_utt[b * D + tid] = acc * inv;
}

// ---------------- sentence GRU step (T=1, h0=0) -> d_out ----------------
__global__ void __launch_bounds__(256, 1)
sent_kernel(const float* __restrict__ Wih, const float* __restrict__ bih,
            const float* __restrict__ bhh, float* __restrict__ out) {
    __shared__ float s_x[D];
    const int b = blockIdx.x, tid = threadIdx.x;
    s_x[tid] = g_utt[b * D + tid];
    __syncthreads();

    float xr = bih[tid], xz = bih[256 + tid], xn = bih[512 + tid];
    const float* wr = Wih + (size_t)tid * D;
    const float* wz = Wih + (size_t)(256 + tid) * D;
    const float* wn = Wih + (size_t)(512 + tid) * D;
#pragma unroll 4
    for (int k = 0; k < D; k += 4) {
        float4 a = *(const float4*)(wr + k);
        xr += a.x * s_x[k] + a.y * s_x[k + 1] + a.z * s_x[k + 2] + a.w * s_x[k + 3];
        float4 c = *(const float4*)(wz + k);
        xz += c.x * s_x[k] + c.y * s_x[k + 1] + c.z * s_x[k + 2] + c.w * s_x[k + 3];
        float4 e = *(const float4*)(wn + k);
        xn += e.x * s_x[k] + e.y * s_x[k + 1] + e.z * s_x[k + 2] + e.w * s_x[k + 3];
    }
    float r = sigmoidf_(xr + bhh[tid]);
    float z = sigmoidf_(xz + bhh[256 + tid]);
    float n = tanhf(xn + r * bhh[512 + tid]);
    out[b * D + tid] = (1.f - z) * n;   // + z*h0, h0 = 0
}

// ---------------- launch ----------------
extern "C" void kernel_launch(void* const* d_in, const int* in_sizes, int n_in,
                              void* d_out, int out_size) {
    const int*   tokens  = (const int*)  d_in[0];
    const float* embed   = (const float*)d_in[1];
    const float* wg_Wih  = (const float*)d_in[2];
    const float* wg_Whh  = (const float*)d_in[3];
    const float* wg_bih  = (const float*)d_in[4];
    const float* wg_bhh  = (const float*)d_in[5];
    const float* ua_w    = (const float*)d_in[6];
    // d_in[7] = ua_b   : softmax-invariant, unused
    const float* sg_Wih  = (const float*)d_in[8];
    // d_in[9] = sg_Whh : multiplied by h0 = 0, unused
    const float* sg_bih  = (const float*)d_in[10];
    const float* sg_bhh  = (const float*)d_in[11];
    // d_in[12..13] = da_w, da_b : softmax over T=1 is identity, unused
    float* out = (float*)d_out;

    reset_kernel<<<1, 128>>>();
    word_kernel<<<GB * GH, WT>>>(tokens, embed, wg_Wih, wg_Whh, wg_bih, wg_bhh);
    pool_kernel<<<NU, 256>>>(ua_w);
    sent_kernel<<<NU, 256>>>(sg_Wih, sg_bih, sg_bhh, out);
}

// round 5
// speedup vs baseline: 1.3586x; 1.3586x over previous
#include <cuda_runtime.h>
#include <math.h>

#define D    256
#define L    512
#define NU   64

// word kernel decomposition: 8 batch groups x 16 hidden slices = 128 CTAs
#define GB   8
#define UPG  8          // utterances per group
#define GH   16
#define HPS  16         // hidden units per slice
#define RPS  48         // gate rows per slice (3*HPS)
#define WT   192        // 6 warps: thread = (row 0..47, upair 0..3)

#define WPAD 260        // Whh row stride (floats)
#define HPAD 264        // h row stride (floats)

typedef unsigned long long ull;

// ---------------- device scratch (static; no allocations) ----------------
__device__ float g_h_hist[(size_t)L * NU * D];     // hidden history (33.5 MB)
__device__ float g_gx[(size_t)L * NU * 768];       // precomputed ih projections (100.7 MB)
__device__ float g_WihT[256 * 768];                // Wih transposed [k][row]
__device__ float g_utt[NU * D];
__device__ int   g_flag[GB * GH];

// ---------------- low-level helpers ----------------
__device__ __forceinline__ ull ffma2(ull a, ull b, ull c) {
    ull d;
    asm("fma.rn.f32x2 %0, %1, %2, %3;" : "=l"(d) : "l"(a), "l"(b), "l"(c));
    return d;
}
__device__ __forceinline__ float2 unpk2(ull v) {
    float2 r;
    asm("mov.b64 {%0, %1}, %2;" : "=f"(r.x), "=f"(r.y) : "l"(v));
    return r;
}
__device__ __forceinline__ ull dupf(float x) {
    ull r;
    asm("mov.b64 %0, {%1, %1};" : "=l"(r) : "f"(x));
    return r;
}
__device__ __forceinline__ int ld_acquire(const int* p) {
    int v;
    asm volatile("ld.acquire.gpu.b32 %0, [%1];" : "=r"(v) : "l"(p) : "memory");
    return v;
}
__device__ __forceinline__ void st_release(int* p, int v) {
    asm volatile("st.release.gpu.b32 [%0], %1;" :: "l"(p), "r"(v) : "memory");
}
__device__ __forceinline__ float sigmoidf_(float x) { return 1.f / (1.f + __expf(-x)); }

// gate row -> global weight row (gate order r, z, n)
__device__ __forceinline__ int gate_row(int i0, int lr) {
    return (lr < 16) ? (i0 + lr)
         : (lr < 32) ? (256 + i0 + (lr - 16))
                     : (512 + i0 + (lr - 32));
}

// ---------------- reset flags ----------------
__global__ void reset_kernel() {
    if (threadIdx.x < GB * GH) g_flag[threadIdx.x] = 0;
}

// ---------------- transpose Wih -> WihT[k][row] ----------------
__global__ void __launch_bounds__(256, 1)
transpose_kernel(const float* __restrict__ Wih) {
    int idx = blockIdx.x * 256 + threadIdx.x;      // 768*256 = 196608
    if (idx < 768 * 256) {
        int n = idx >> 8, k = idx & 255;           // read coalesced over k
        g_WihT[k * 768 + n] = Wih[idx];
    }
}

// ---------------- ih projection GEMM: gx[m=t*64+b][row] = emb . Wih^T ----------------
// tile: BM=64 (one t, all 64 b), BN=128 rows, BK=64; 256 threads, thread tile 4m x 8n
#define GA_S 68          // A_s row stride  (A_s[m][GA_S])
#define GB_S 132         // B_s row stride  (B_s[k][GB_S])
#define GEMM_SMEM_BYTES ((64 * GA_S + 64 * GB_S) * 4)

__global__ void __launch_bounds__(256, 2)
ih_gemm_kernel(const int* __restrict__ tokens, const float* __restrict__ embed) {
    extern __shared__ float gsm[];
    float* A_s = gsm;                    // [64][GA_S]
    float* B_s = gsm + 64 * GA_S;        // [64][GB_S]
    __shared__ int tok_s[64];

    const int tid = threadIdx.x;
    const int t   = blockIdx.y;          // m-tile = all 64 b's of timestep t
    const int NB0 = blockIdx.x * 128;

    if (tid < 64) tok_s[tid] = tokens[tid * L + t];   // tokens[b][t]

    const int tm = tid >> 4;             // 0..15 -> m0 = tm*4
    const int tn = tid & 15;             // 0..15 -> n0 = tn*8
    const int m0 = tm * 4, n0 = tn * 8;

    ull c[4][4];
#pragma unroll
    for (int i = 0; i < 4; ++i)
#pragma unroll
        for (int j = 0; j < 4; ++j) c[i][j] = 0ull;

    for (int kb = 0; kb < 4; ++kb) {
        __syncthreads();
        // stage A (natural [m][k]): 1024 float4
#pragma unroll
        for (int it = 0; it < 4; ++it) {
            int idx = tid + it * 256;
            int m = idx >> 4, kq = idx & 15;
            float4 v = *(const float4*)(embed + (size_t)tok_s[m] * 256 + kb * 64 + kq * 4);
            *(float4*)&A_s[m * GA_S + kq * 4] = v;
        }
        // stage B (transposed [k][n]) from WihT, coalesced
#pragma unroll
        for (int it = 0; it < 8; ++it) {
            int idx = tid + it * 256;
            int k = idx >> 5, nq = idx & 31;
            float4 v = *(const float4*)(g_WihT + (size_t)(kb * 64 + k) * 768 + NB0 + nq * 4);
            *(float4*)&B_s[k * GB_S + nq * 4] = v;
        }
        __syncthreads();

#pragma unroll 8
        for (int k = 0; k < 64; ++k) {
            ull ad0 = dupf(A_s[(m0 + 0) * GA_S + k]);
            ull ad1 = dupf(A_s[(m0 + 1) * GA_S + k]);
            ull ad2 = dupf(A_s[(m0 + 2) * GA_S + k]);
            ull ad3 = dupf(A_s[(m0 + 3) * GA_S + k]);
            const ulonglong2* bp = (const ulonglong2*)&B_s[k * GB_S + n0];
            ulonglong2 b0 = bp[0], b1 = bp[1];
            c[0][0] = ffma2(ad0, b0.x, c[0][0]);
            c[0][1] = ffma2(ad0, b0.y, c[0][1]);
            c[0][2] = ffma2(ad0, b1.x, c[0][2]);
            c[0][3] = ffma2(ad0, b1.y, c[0][3]);
            c[1][0] = ffma2(ad1, b0.x, c[1][0]);
            c[1][1] = ffma2(ad1, b0.y, c[1][1]);
            c[1][2] = ffma2(ad1, b1.x, c[1][2]);
            c[1][3] = ffma2(ad1, b1.y, c[1][3]);
            c[2][0] = ffma2(ad2, b0.x, c[2][0]);
            c[2][1] = ffma2(ad2, b0.y, c[2][1]);
            c[2][2] = ffma2(ad2, b1.x, c[2][2]);
            c[2][3] = ffma2(ad2, b1.y, c[2][3]);
            c[3][0] = ffma2(ad3, b0.x, c[3][0]);
            c[3][1] = ffma2(ad3, b0.y, c[3][1]);
            c[3][2] = ffma2(ad3, b1.x, c[3][2]);
            c[3][3] = ffma2(ad3, b1.y, c[3][3]);
        }
    }

    // write 4m x 8n
#pragma unroll
    for (int i = 0; i < 4; ++i) {
        float v[8];
#pragma unroll
        for (int j = 0; j < 4; ++j) {
            float2 p = unpk2(c[i][j]);
            v[2 * j] = p.x;
            v[2 * j + 1] = p.y;
        }
        float* dst = g_gx + ((size_t)t * 64 + m0 + i) * 768 + NB0 + n0;
        *(float4*)dst       = make_float4(v[0], v[1], v[2], v[3]);
        *(float4*)(dst + 4) = make_float4(v[4], v[5], v[6], v[7]);
    }
}

// ---------------- word GRU sequential kernel (hh only) ----------------
// SMEM (floats): whh[48][260]@0, h[8][264]@12480, g[48*8]@14592, bih[48]@14976, bhh[48]@15024
#define OFF_WHH 0
#define OFF_H   12480
#define OFF_G   14592
#define OFF_BIH 14976
#define OFF_BHH 15024
#define WORD_SMEM_BYTES (15072 * 4)

__global__ void __launch_bounds__(WT, 1)
word_kernel(const float* __restrict__ Whh,
            const float* __restrict__ bih, const float* __restrict__ bhh) {
    extern __shared__ float sm[];
    float* s_whh = sm + OFF_WHH;
    float* s_h   = sm + OFF_H;
    float* s_g   = sm + OFF_G;
    float* s_bih = sm + OFF_BIH;
    float* s_bhh = sm + OFF_BHH;

    const int g    = blockIdx.x >> 4;
    const int sl   = blockIdx.x & 15;
    const int i0   = sl * HPS;
    const int b0   = g * UPG;
    const int tid  = threadIdx.x;
    const int wp   = tid >> 5;          // 0..5
    const int lane = tid & 31;
    const int r    = tid >> 2;          // gate row in slice (0..47); warp: 8 rows
    const int p    = tid & 3;           // utterance pair slot

    // prologue: resident Whh slice + biases; zero h
    for (int idx = tid; idx < RPS * D; idx += WT) {
        int rr = idx >> 8, k = idx & 255;
        s_whh[rr * WPAD + k] = Whh[(size_t)gate_row(i0, rr) * D + k];
    }
    if (tid < RPS) {
        int grow = gate_row(i0, tid);
        s_bih[tid] = bih[grow];
        s_bhh[tid] = bhh[grow];
    }
    for (int idx = tid; idx < UPG * HPAD; idx += WT) s_h[idx] = 0.f;
    __syncthreads();

    const float mybhh = s_bhh[r];
    const int   ii = tid & 15, uu = tid >> 4;   // epilogue mapping (tid<128)

    for (int t = 0; t < L; ++t) {
        // (A) prefetch gx[t] rows for the epilogue (LDG issued before poll)
        float gxr = 0.f, gxz = 0.f, gxn = 0.f;
        if (tid < 128) {
            const float* gb = g_gx + ((size_t)t * NU + b0 + uu) * 768 + i0 + ii;
            gxr = gb[0];
            gxz = gb[256];
            gxn = gb[512];
        }

        // (B) wait for h_{t-1}: one warp, one lane per flag (parallel poll)
        if (t > 0) {
            if (wp == 0 && lane < GH) {
                const int* fp = &g_flag[g * GH + lane];
                while (ld_acquire(fp) < t) { }
            }
            __syncthreads();
            // stage h: 8KB, 512 float4, 192 threads
            const float4* src = (const float4*)(g_h_hist + (size_t)(t - 1) * NU * D + (size_t)b0 * D);
            for (int idx = tid; idx < 512; idx += WT) {
                int su = idx >> 6, k4 = idx & 63;
                *(float4*)(s_h + su * HPAD + k4 * 4) = src[idx];
            }
            __syncthreads();
        }

        // (C) hh GEMV: row r against utts p and p+4
        ull a0 = 0ull, a1 = 0ull, c0 = 0ull, c1 = 0ull;
        const ulonglong2* W  = (const ulonglong2*)(s_whh + r * WPAD);
        const ulonglong2* HA = (const ulonglong2*)(s_h + p * HPAD);
        const ulonglong2* HB = (const ulonglong2*)(s_h + (p + 4) * HPAD);
#pragma unroll 8
        for (int kc = 0; kc < 64; ++kc) {
            ulonglong2 w  = W[kc];
            ulonglong2 ha = HA[kc];
            ulonglong2 hb = HB[kc];
            a0 = ffma2(w.x, ha.x, a0);
            a1 = ffma2(w.y, ha.y, a1);
            c0 = ffma2(w.x, hb.x, c0);
            c1 = ffma2(w.y, hb.y, c1);
        }
        {
            float2 f0 = unpk2(a0), f1 = unpk2(a1);
            s_g[r * 8 + p] = (f0.x + f0.y) + (f1.x + f1.y) + mybhh;
            f0 = unpk2(c0); f1 = unpk2(c1);
            s_g[r * 8 + p + 4] = (f0.x + f0.y) + (f1.x + f1.y) + mybhh;
        }
        __syncthreads();

        // (D) gates + hidden update + publish
        if (tid < 128) {
            float hr = s_g[ii * 8 + uu];
            float hz = s_g[(16 + ii) * 8 + uu];
            float hn = s_g[(32 + ii) * 8 + uu];
            float rg = sigmoidf_(gxr + s_bih[ii] + hr);
            float zg = sigmoidf_(gxz + s_bih[16 + ii] + hz);
            float ng = tanhf(gxn + s_bih[32 + ii] + rg * hn);
            float hprev = s_h[uu * HPAD + i0 + ii];
            float hnew = (1.f - zg) * ng + zg * hprev;
            g_h_hist[(size_t)t * NU * D + (size_t)(b0 + uu) * D + (i0 + ii)] = hnew;
        }
        __syncthreads();
        if (tid == 0) {
            __threadfence();
            st_release(&g_flag[g * GH + sl], t + 1);
        }
    }
}

// ---------------- word-level attention pool: h_hist -> g_utt ----------------
__global__ void __launch_bounds__(256, 1)
pool_kernel(const float* __restrict__ ua_w) {
    __shared__ float s_w[D];
    __shared__ float s_l[L];
    __shared__ float s_red[32];
    const int b = blockIdx.x, tid = threadIdx.x;
    const int lane = tid & 31, wpp = tid >> 5;

    s_w[tid] = ua_w[tid];
    __syncthreads();

    const float* base = g_h_hist + (size_t)b * D;
    for (int tt = 0; tt < 64; ++tt) {
        int t = wpp * 64 + tt;
        const float* row = base + (size_t)t * NU * D;
        float pv = 0.f;
#pragma unroll
        for (int j = 0; j < 8; ++j) pv += row[lane + 32 * j] * s_w[lane + 32 * j];
        for (int off = 16; off; off >>= 1) pv += __shfl_down_sync(0xffffffffu, pv, off);
        if (lane == 0) s_l[t] = pv;   // ua_b omitted: softmax-invariant
    }
    __syncthreads();

    float m = -1e30f;
    for (int t = tid; t < L; t += 256) m = fmaxf(m, s_l[t]);
    for (int off = 16; off; off >>= 1) m = fmaxf(m, __shfl_xor_sync(0xffffffffu, m, off));
    if (lane == 0) s_red[wpp] = m;
    __syncthreads();
    if (tid == 0) {
        float mm = s_red[0];
#pragma unroll
        for (int i = 1; i < 8; ++i) mm = fmaxf(mm, s_red[i]);
        s_red[16] = mm;
    }
    __syncthreads();
    m = s_red[16];
    float ssum = 0.f;
    for (int t = tid; t < L; t += 256) {
        float e = expf(s_l[t] - m);
        s_l[t] = e;
        ssum += e;
    }
    for (int off = 16; off; off >>= 1) ssum += __shfl_xor_sync(0xffffffffu, ssum, off);
    if (lane == 0) s_red[wpp] = ssum;
    __syncthreads();
    if (tid == 0) {
        float ss = 0.f;
#pragma unroll
        for (int i = 0; i < 8; ++i) ss += s_red[i];
        s_red[17] = ss;
    }
    __syncthreads();
    const float inv = 1.f / s_red[17];

    float acc = 0.f;
#pragma unroll 8
    for (int t = 0; t < L; ++t) acc += s_l[t] * base[(size_t)t * NU * D + tid];
    g_utt[b * D + tid] = acc * inv;
}

// ---------------- sentence GRU step (T=1, h0=0) -> d_out ----------------
__global__ void __launch_bounds__(256, 1)
sent_kernel(const float* __restrict__ Wih, const float* __restrict__ bih,
            const float* __restrict__ bhh, float* __restrict__ out) {
    __shared__ float s_x[D];
    const int b = blockIdx.x, tid = threadIdx.x;
    s_x[tid] = g_utt[b * D + tid];
    __syncthreads();

    float xr = bih[tid], xz = bih[256 + tid], xn = bih[512 + tid];
    const float* wr = Wih + (size_t)tid * D;
    const float* wz = Wih + (size_t)(256 + tid) * D;
    const float* wn = Wih + (size_t)(512 + tid) * D;
#pragma unroll 4
    for (int k = 0; k < D; k += 4) {
        float4 a = *(const float4*)(wr + k);
        xr += a.x * s_x[k] + a.y * s_x[k + 1] + a.z * s_x[k + 2] + a.w * s_x[k + 3];
        float4 c = *(const float4*)(wz + k);
        xz += c.x * s_x[k] + c.y * s_x[k + 1] + c.z * s_x[k + 2] + c.w * s_x[k + 3];
        float4 e = *(const float4*)(wn + k);
        xn += e.x * s_x[k] + e.y * s_x[k + 1] + e.z * s_x[k + 2] + e.w * s_x[k + 3];
    }
    float r = sigmoidf_(xr + bhh[tid]);
    float z = sigmoidf_(xz + bhh[256 + tid]);
    float n = tanhf(xn + r * bhh[512 + tid]);
    out[b * D + tid] = (1.f - z) * n;   // + z*h0, h0 = 0
}

// ---------------- launch ----------------
extern "C" void kernel_launch(void* const* d_in, const int* in_sizes, int n_in,
                              void* d_out, int out_size) {
    const int*   tokens  = (const int*)  d_in[0];
    const float* embed   = (const float*)d_in[1];
    const float* wg_Wih  = (const float*)d_in[2];
    const float* wg_Whh  = (const float*)d_in[3];
    const float* wg_bih  = (const float*)d_in[4];
    const float* wg_bhh  = (const float*)d_in[5];
    const float* ua_w    = (const float*)d_in[6];
    // d_in[7] = ua_b   : softmax-invariant, unused
    const float* sg_Wih  = (const float*)d_in[8];
    // d_in[9] = sg_Whh : multiplied by h0 = 0, unused
    const float* sg_bih  = (const float*)d_in[10];
    const float* sg_bhh  = (const float*)d_in[11];
    // d_in[12..13] = da_w, da_b : softmax over T=1 is identity, unused
    float* out = (float*)d_out;

    cudaFuncSetAttribute(word_kernel, cudaFuncAttributeMaxDynamicSharedMemorySize,
                         WORD_SMEM_BYTES);
    cudaFuncSetAttribute(ih_gemm_kernel, cudaFuncAttributeMaxDynamicSharedMemorySize,
                         GEMM_SMEM_BYTES);

    reset_kernel<<<1, 128>>>();
    transpose_kernel<<<768, 256>>>(wg_Wih);
    dim3 ggrid(6, 512);
    ih_gemm_kernel<<<ggrid, 256, GEMM_SMEM_BYTES>>>(tokens, embed);
    word_kernel<<<GB * GH, WT, WORD_SMEM_BYTES>>>(wg_Whh, wg_bih, wg_bhh);
    pool_kernel<<<NU, 256>>>(ua_w);
    sent_kernel<<<NU, 256>>>(sg_Wih, sg_bih, sg_bhh, out);
}

// round 6
// speedup vs baseline: 2.8272x; 2.0810x over previous
#include <cuda_runtime.h>
#include <math.h>
#include <stdint.h>

#define D    256
#define L    512
#define NU   64

// word kernel: 32 clusters x 4 CTAs; cluster owns 2 utterances, CTA owns 64 hidden units
#define CPG  4          // CTAs per cluster (hidden split)
#define UPC  2          // utterances per cluster
#define ROWS 192        // gate rows per CTA (3 * 64)
#define WT   384        // 12 warps

typedef unsigned long long ull;

// ---------------- device scratch (static; no allocations) ----------------
__device__ float g_h_hist[(size_t)L * NU * D];     // hidden history (33.5 MB)
__device__ float g_gx[(size_t)L * NU * 768];       // precomputed ih projections (100.7 MB)
__device__ float g_WihT[256 * 768];                // Wih transposed [k][row]
__device__ float g_utt[NU * D];

// ---------------- low-level helpers ----------------
__device__ __forceinline__ ull ffma2(ull a, ull b, ull c) {
    ull d;
    asm("fma.rn.f32x2 %0, %1, %2, %3;" : "=l"(d) : "l"(a), "l"(b), "l"(c));
    return d;
}
__device__ __forceinline__ float2 unpk2(ull v) {
    float2 r;
    asm("mov.b64 {%0, %1}, %2;" : "=f"(r.x), "=f"(r.y) : "l"(v));
    return r;
}
__device__ __forceinline__ ull dupf(float x) {
    ull r;
    asm("mov.b64 %0, {%1, %1};" : "=l"(r) : "f"(x));
    return r;
}
__device__ __forceinline__ uint32_t smem_u32(const void* p) {
    uint32_t a;
    asm("{ .reg .u64 t; cvta.to.shared.u64 t, %1; cvt.u32.u64 %0, t; }" : "=r"(a) : "l"(p));
    return a;
}
__device__ __forceinline__ uint32_t ctarank() {
    uint32_t r;
    asm("mov.u32 %0, %%cluster_ctarank;" : "=r"(r));
    return r;
}
#define CLU_ARRIVE() asm volatile("barrier.cluster.arrive.aligned;" ::: "memory")
#define CLU_WAIT()   asm volatile("barrier.cluster.wait.aligned;" ::: "memory")

__device__ __forceinline__ float sigmoidf_(float x) { return 1.f / (1.f + __expf(-x)); }

// ---------------- transpose Wih -> WihT[k][row] ----------------
__global__ void __launch_bounds__(256, 1)
transpose_kernel(const float* __restrict__ Wih) {
    int idx = blockIdx.x * 256 + threadIdx.x;      // 768*256
    if (idx < 768 * 256) {
        int n = idx >> 8, k = idx & 255;
        g_WihT[k * 768 + n] = Wih[idx];
    }
}

// ---------------- ih projection GEMM: gx[t*64+b][row] = emb . Wih^T ----------------
#define GA_S 68
#define GB_S 132
#define GEMM_SMEM_BYTES ((64 * GA_S + 64 * GB_S) * 4)

__global__ void __launch_bounds__(256, 2)
ih_gemm_kernel(const int* __restrict__ tokens, const float* __restrict__ embed) {
    extern __shared__ float gsm[];
    float* A_s = gsm;                    // [64][GA_S]
    float* B_s = gsm + 64 * GA_S;        // [64][GB_S]
    __shared__ int tok_s[64];

    const int tid = threadIdx.x;
    const int t   = blockIdx.y;
    const int NB0 = blockIdx.x * 128;

    if (tid < 64) tok_s[tid] = tokens[tid * L + t];

    const int tm = tid >> 4, tn = tid & 15;
    const int m0 = tm * 4, n0 = tn * 8;

    ull c[4][4];
#pragma unroll
    for (int i = 0; i < 4; ++i)
#pragma unroll
        for (int j = 0; j < 4; ++j) c[i][j] = 0ull;

    for (int kb = 0; kb < 4; ++kb) {
        __syncthreads();
#pragma unroll
        for (int it = 0; it < 4; ++it) {
            int idx = tid + it * 256;
            int m = idx >> 4, kq = idx & 15;
            float4 v = *(const float4*)(embed + (size_t)tok_s[m] * 256 + kb * 64 + kq * 4);
            *(float4*)&A_s[m * GA_S + kq * 4] = v;
        }
#pragma unroll
        for (int it = 0; it < 8; ++it) {
            int idx = tid + it * 256;
            int k = idx >> 5, nq = idx & 31;
            float4 v = *(const float4*)(g_WihT + (size_t)(kb * 64 + k) * 768 + NB0 + nq * 4);
            *(float4*)&B_s[k * GB_S + nq * 4] = v;
        }
        __syncthreads();

#pragma unroll 8
        for (int k = 0; k < 64; ++k) {
            ull ad0 = dupf(A_s[(m0 + 0) * GA_S + k]);
            ull ad1 = dupf(A_s[(m0 + 1) * GA_S + k]);
            ull ad2 = dupf(A_s[(m0 + 2) * GA_S + k]);
            ull ad3 = dupf(A_s[(m0 + 3) * GA_S + k]);
            const ulonglong2* bp = (const ulonglong2*)&B_s[k * GB_S + n0];
            ulonglong2 b0 = bp[0], b1 = bp[1];
            c[0][0] = ffma2(ad0, b0.x, c[0][0]);
            c[0][1] = ffma2(ad0, b0.y, c[0][1]);
            c[0][2] = ffma2(ad0, b1.x, c[0][2]);
            c[0][3] = ffma2(ad0, b1.y, c[0][3]);
            c[1][0] = ffma2(ad1, b0.x, c[1][0]);
            c[1][1] = ffma2(ad1, b0.y, c[1][1]);
            c[1][2] = ffma2(ad1, b1.x, c[1][2]);
            c[1][3] = ffma2(ad1, b1.y, c[1][3]);
            c[2][0] = ffma2(ad2, b0.x, c[2][0]);
            c[2][1] = ffma2(ad2, b0.y, c[2][1]);
            c[2][2] = ffma2(ad2, b1.x, c[2][2]);
            c[2][3] = ffma2(ad2, b1.y, c[2][3]);
            c[3][0] = ffma2(ad3, b0.x, c[3][0]);
            c[3][1] = ffma2(ad3, b0.y, c[3][1]);
            c[3][2] = ffma2(ad3, b1.x, c[3][2]);
            c[3][3] = ffma2(ad3, b1.y, c[3][3]);
        }
    }

#pragma unroll
    for (int i = 0; i < 4; ++i) {
        float v[8];
#pragma unroll
        for (int j = 0; j < 4; ++j) {
            float2 p = unpk2(c[i][j]);
            v[2 * j] = p.x;
            v[2 * j + 1] = p.y;
        }
        float* dst = g_gx + ((size_t)t * 64 + m0 + i) * 768 + NB0 + n0;
        *(float4*)dst       = make_float4(v[0], v[1], v[2], v[3]);
        *(float4*)(dst + 4) = make_float4(v[4], v[5], v[6], v[7]);
    }
}

// ---------------- word GRU: cluster kernel, DSMEM h-exchange ----------------
// dynamic SMEM (floats):
//  W_s (permuted Whh slice) @0       : 49152
//  s_h double-buffer        @49152   : 2 * (2 utts * 8 kq * 36) = 1152
//  s_g (hh preacts + bhh)   @50304   : 384
//  s_bih                    @50688   : 192
//  s_bhh                    @50880   : 192   -> 51072 floats = 204288 B
#define OFF_H   49152
#define OFF_G   50304
#define OFF_BI  50688
#define OFF_BH  50880
#define WORD_SMEM_BYTES (51072 * 4)

__global__ void __launch_bounds__(WT, 1) __cluster_dims__(CPG, 1, 1)
word_kernel(const float* __restrict__ Whh,
            const float* __restrict__ bih, const float* __restrict__ bhh) {
    extern __shared__ float sm[];
    float* W_s   = sm;
    float* s_h   = sm + OFF_H;
    float* s_g   = sm + OFF_G;
    float* s_bih = sm + OFF_BI;
    float* s_bhh = sm + OFF_BH;

    const int c   = (int)ctarank();        // hidden chunk [c*64, c*64+64)
    const int cl  = blockIdx.x >> 2;       // cluster id
    const int b0  = cl * UPC;              // first utterance
    const int tid = threadIdx.x;

    // thread decomposition for the dot: rg (8-row group), kq (k-eighth), u (utt)
    const int rg  = tid >> 4;              // 0..23
    const int kq  = (tid >> 1) & 7;        // 0..7
    const int u   = tid & 1;               // 0..1
    const int w   = tid >> 5;              // warp 0..11
    const int rgl = rg & 1;

    // ---- prologue: permuted weight fill + biases + zero h buf0 ----
    for (int q = tid; q < ROWS * 64; q += WT) {      // q = float4 index
        int lr = q >> 6;                             // local gate row 0..191
        int k  = (q & 63) * 4;
        int kqq = k >> 5, j = (k >> 2) & 7;
        int ww = lr >> 4, rl = (lr >> 3) & 1, ii = lr & 7;
        int grow = (lr < 64) ? c * 64 + lr
                 : (lr < 128) ? 256 + c * 64 + (lr - 64)
                              : 512 + c * 64 + (lr - 128);
        float4 v = *(const float4*)(Whh + (size_t)grow * D + k);
        int chunk = ((ww * 8 + ii) * 8 + j) * 16 + rl * 8 + kqq;
        *(float4*)(W_s + chunk * 4) = v;
    }
    if (tid < ROWS) {
        int lr = tid;
        int grow = (lr < 64) ? c * 64 + lr
                 : (lr < 128) ? 256 + c * 64 + (lr - 64)
                              : 512 + c * 64 + (lr - 128);
        s_bih[lr] = bih[grow];
        s_bhh[lr] = bhh[grow];
    }
    for (int q = tid; q < 576; q += WT) s_h[q] = 0.f;   // zero buf0
    __syncthreads();
    CLU_ARRIVE();
    CLU_WAIT();

    const ulonglong2* Wb = ((const ulonglong2*)W_s) + (w * 1024 + rgl * 8 + kq);
    const int ue = tid >> 6, ie = tid & 63;            // epilogue mapping (tid<128)
    const int kg = c * 2 + (ie >> 5), off = ie & 31;   // own h position

    for (int t = 0; t < L; ++t) {
        const int buf = t & 1;

        // (A) gx prefetch for this step (LDG issued before the cluster wait)
        float gxr = 0.f, gxz = 0.f, gxn = 0.f;
        if (tid < 128) {
            const float* gp = g_gx + ((size_t)t * NU + b0 + ue) * 768 + c * 64 + ie;
            gxr = gp[0];
            gxz = gp[256];
            gxn = gp[512];
        }

        // (B) wait for h_{t-1} from all cluster CTAs (skip at t=0: buf0 zeroed)
        if (t > 0) CLU_WAIT();

        // (C) hh GEMV: 8 rows x 1 utt x 32 k per thread, weights streamed at crossbar floor
        ull acc[8];
#pragma unroll
        for (int i = 0; i < 8; ++i) acc[i] = 0ull;
        const ulonglong2* xb = (const ulonglong2*)(s_h + buf * 576) + (u * 8 + kq) * 9;
#pragma unroll
        for (int j = 0; j < 8; ++j) {
            ulonglong2 xv = xb[j];
#pragma unroll
            for (int i = 0; i < 8; ++i) {
                ulonglong2 wv = Wb[(i * 8 + j) * 16];
                acc[i] = ffma2(wv.x, xv.x, acc[i]);
                acc[i] = ffma2(wv.y, xv.y, acc[i]);
            }
        }

        // (D) reduce across kq lanes (butterfly over lane bits 1..3)
        float v[8];
#pragma unroll
        for (int i = 0; i < 8; ++i) {
            float2 p = unpk2(acc[i]);
            v[i] = p.x + p.y;
        }
#pragma unroll
        for (int m = 2; m <= 8; m <<= 1)
#pragma unroll
            for (int i = 0; i < 8; ++i)
                v[i] += __shfl_xor_sync(0xffffffffu, v[i], m);
        if (kq == 0) {
            int lrb = rg * 8;
#pragma unroll
            for (int i = 0; i < 8; ++i)
                s_g[(lrb + i) * 2 + u] = v[i] + s_bhh[lrb + i];
        }
        __syncthreads();

        // (E) gates + hidden update + DSMEM broadcast + hist store
        if (tid < 128) {
            float hr = s_g[ie * 2 + ue];
            float hz = s_g[(64 + ie) * 2 + ue];
            float hn = s_g[(128 + ie) * 2 + ue];
            float r = sigmoidf_(gxr + s_bih[ie] + hr);
            float z = sigmoidf_(gxz + s_bih[64 + ie] + hz);
            float n = tanhf(gxn + s_bih[128 + ie] + r * hn);
            float hprev = s_h[buf * 576 + (ue * 8 + kg) * 36 + off];
            float hnew = (1.f - z) * n + z * hprev;
            g_h_hist[((size_t)t * NU + b0 + ue) * D + c * 64 + ie] = hnew;
            uint32_t a = smem_u32(s_h + (buf ^ 1) * 576 + (ue * 8 + kg) * 36 + off);
#pragma unroll
            for (int pr = 0; pr < CPG; ++pr) {
                uint32_t ra;
                asm volatile("mapa.shared::cluster.u32 %0, %1, %2;"
                             : "=r"(ra) : "r"(a), "r"(pr));
                asm volatile("st.shared::cluster.f32 [%0], %1;"
                             :: "r"(ra), "f"(hnew) : "memory");
            }
        }

        // (F) release this step's h writes to the cluster
        CLU_ARRIVE();
    }
    CLU_WAIT();   // no CTA exits while peers' stores to its SMEM may be in flight
}

// ---------------- word-level attention pool: h_hist -> g_utt ----------------
__global__ void __launch_bounds__(256, 1)
pool_kernel(const float* __restrict__ ua_w) {
    __shared__ float s_w[D];
    __shared__ float s_l[L];
    __shared__ float s_red[32];
    const int b = blockIdx.x, tid = threadIdx.x;
    const int lane = tid & 31, wpp = tid >> 5;

    s_w[tid] = ua_w[tid];
    __syncthreads();

    const float* base = g_h_hist + (size_t)b * D;
    for (int tt = 0; tt < 64; ++tt) {
        int t = wpp * 64 + tt;
        const float* row = base + (size_t)t * NU * D;
        float pv = 0.f;
#pragma unroll
        for (int j = 0; j < 8; ++j) pv += row[lane + 32 * j] * s_w[lane + 32 * j];
        for (int off = 16; off; off >>= 1) pv += __shfl_down_sync(0xffffffffu, pv, off);
        if (lane == 0) s_l[t] = pv;   // ua_b omitted: softmax-invariant
    }
    __syncthreads();

    float m = -1e30f;
    for (int t = tid; t < L; t += 256) m = fmaxf(m, s_l[t]);
    for (int off = 16; off; off >>= 1) m = fmaxf(m, __shfl_xor_sync(0xffffffffu, m, off));
    if (lane == 0) s_red[wpp] = m;
    __syncthreads();
    if (tid == 0) {
        float mm = s_red[0];
#pragma unroll
        for (int i = 1; i < 8; ++i) mm = fmaxf(mm, s_red[i]);
        s_red[16] = mm;
    }
    __syncthreads();
    m = s_red[16];
    float ssum = 0.f;
    for (int t = tid; t < L; t += 256) {
        float e = expf(s_l[t] - m);
        s_l[t] = e;
        ssum += e;
    }
    for (int off = 16; off; off >>= 1) ssum += __shfl_xor_sync(0xffffffffu, ssum, off);
    if (lane == 0) s_red[wpp] = ssum;
    __syncthreads();
    if (tid == 0) {
        float ss = 0.f;
#pragma unroll
        for (int i = 0; i < 8; ++i) ss += s_red[i];
        s_red[17] = ss;
    }
    __syncthreads();
    const float inv = 1.f / s_red[17];

    float acc = 0.f;
#pragma unroll 8
    for (int t = 0; t < L; ++t) acc += s_l[t] * base[(size_t)t * NU * D + tid];
    g_utt[b * D + tid] = acc * inv;
}

// ---------------- sentence GRU step (T=1, h0=0) -> d_out ----------------
__global__ void __launch_bounds__(256, 1)
sent_kernel(const float* __restrict__ Wih, const float* __restrict__ bih,
            const float* __restrict__ bhh, float* __restrict__ out) {
    __shared__ float s_x[D];
    const int b = blockIdx.x, tid = threadIdx.x;
    s_x[tid] = g_utt[b * D + tid];
    __syncthreads();

    float xr = bih[tid], xz = bih[256 + tid], xn = bih[512 + tid];
    const float* wr = Wih + (size_t)tid * D;
    const float* wz = Wih + (size_t)(256 + tid) * D;
    const float* wn = Wih + (size_t)(512 + tid) * D;
#pragma unroll 4
    for (int k = 0; k < D; k += 4) {
        float4 a = *(const float4*)(wr + k);
        xr += a.x * s_x[k] + a.y * s_x[k + 1] + a.z * s_x[k + 2] + a.w * s_x[k + 3];
        float4 c = *(const float4*)(wz + k);
        xz += c.x * s_x[k] + c.y * s_x[k + 1] + c.z * s_x[k + 2] + c.w * s_x[k + 3];
        float4 e = *(const float4*)(wn + k);
        xn += e.x * s_x[k] + e.y * s_x[k + 1] + e.z * s_x[k + 2] + e.w * s_x[k + 3];
    }
    float r = sigmoidf_(xr + bhh[tid]);
    float z = sigmoidf_(xz + bhh[256 + tid]);
    float n = tanhf(xn + r * bhh[512 + tid]);
    out[b * D + tid] = (1.f - z) * n;   // + z*h0, h0 = 0
}

// ---------------- launch ----------------
extern "C" void kernel_launch(void* const* d_in, const int* in_sizes, int n_in,
                              void* d_out, int out_size) {
    const int*   tokens  = (const int*)  d_in[0];
    const float* embed   = (const float*)d_in[1];
    const float* wg_Wih  = (const float*)d_in[2];
    const float* wg_Whh  = (const float*)d_in[3];
    const float* wg_bih  = (const float*)d_in[4];
    const float* wg_bhh  = (const float*)d_in[5];
    const float* ua_w    = (const float*)d_in[6];
    // d_in[7] = ua_b   : softmax-invariant, unused
    const float* sg_Wih  = (const float*)d_in[8];
    // d_in[9] = sg_Whh : multiplied by h0 = 0, unused
    const float* sg_bih  = (const float*)d_in[10];
    const float* sg_bhh  = (const float*)d_in[11];
    // d_in[12..13] = da_w, da_b : softmax over T=1 is identity, unused
    float* out = (float*)d_out;

    cudaFuncSetAttribute(word_kernel, cudaFuncAttributeMaxDynamicSharedMemorySize,
                         WORD_SMEM_BYTES);
    cudaFuncSetAttribute(ih_gemm_kernel, cudaFuncAttributeMaxDynamicSharedMemorySize,
                         GEMM_SMEM_BYTES);

    transpose_kernel<<<768, 256>>>(wg_Wih);
    dim3 ggrid(6, 512);
    ih_gemm_kernel<<<ggrid, 256, GEMM_SMEM_BYTES>>>(tokens, embed);
    word_kernel<<<32 * CPG, WT, WORD_SMEM_BYTES>>>(wg_Whh, wg_bih, wg_bhh);
    pool_kernel<<<NU, 256>>>(ua_w);
    sent_kernel<<<NU, 256>>>(sg_Wih, sg_bih, sg_bhh, out);
}